// round 7
// baseline (speedup 1.0000x reference)
#include <cuda_runtime.h>
#include <cuda_bf16.h>
#include <cuda_fp16.h>
#include <cstdint>
#include <cstddef>

#define N_NODES 100000
#define N_EDGES 600000
#define D 128
#define BN_EPS 1e-5f

// ---------------- scratch (static device globals; no allocation) ----------------
// Accumulators in PERMUTED fragment layout (fp16). Per row: 16 uint4; uint4 index
// u = tp*4 + g (tp=0..3 kstep-pair, g=0..3 lane-k-group). Halves within uint4:
// [t=2tp: K=32tp+2g,+1 | +8,+9 | t=2tp+1: K=32tp+16+2g,+1 | +8,+9]
__device__ __half2 g_acc_o[(size_t)N_NODES * 64];
__device__ __half2 g_acc_i[(size_t)N_NODES * 64];
__device__ float  g_cnt[2 * N_NODES];               // [0:N) in-deg(dst), [N:2N) deg at src
// B fragments: [kstep 0..23][ntile 0..15][lane 0..31] = (b0h,b1h,b0l,b1l)
// ksteps 0..15: fp16 hi/lo split;  ksteps 16..23: bf16 hi/lo split
__device__ uint4  g_Bfrag[24 * 16 * 32];
__device__ float  g_bias[D];
__device__ double g_sum[D];
__device__ double g_sumsq[D];
__device__ float  g_scale[D];
__device__ float  g_shift[D];

// ---------------- helpers ----------------
__device__ __forceinline__ void red_add_h2v4(__half2* p, __half2 a, __half2 b,
                                             __half2 c, __half2 d) {
    asm volatile("red.global.add.noftz.v4.f16x2 [%0], {%1,%2,%3,%4};"
                 :: "l"(p),
                    "r"(*reinterpret_cast<uint32_t*>(&a)),
                    "r"(*reinterpret_cast<uint32_t*>(&b)),
                    "r"(*reinterpret_cast<uint32_t*>(&c)),
                    "r"(*reinterpret_cast<uint32_t*>(&d)) : "memory");
}

__device__ __forceinline__ void mma_bf(float* d, uint32_t a0, uint32_t a1, uint32_t a2,
                                       uint32_t a3, uint32_t b0, uint32_t b1) {
    asm volatile(
        "mma.sync.aligned.m16n8k16.row.col.f32.bf16.bf16.f32 "
        "{%0,%1,%2,%3}, {%4,%5,%6,%7}, {%8,%9}, {%0,%1,%2,%3};"
        : "+f"(d[0]), "+f"(d[1]), "+f"(d[2]), "+f"(d[3])
        : "r"(a0), "r"(a1), "r"(a2), "r"(a3), "r"(b0), "r"(b1));
}

__device__ __forceinline__ void mma_fp16(float* d, uint32_t a0, uint32_t a1, uint32_t a2,
                                         uint32_t a3, uint32_t b0, uint32_t b1) {
    asm volatile(
        "mma.sync.aligned.m16n8k16.row.col.f32.f16.f16.f32 "
        "{%0,%1,%2,%3}, {%4,%5,%6,%7}, {%8,%9}, {%0,%1,%2,%3};"
        : "+f"(d[0]), "+f"(d[1]), "+f"(d[2]), "+f"(d[3])
        : "r"(a0), "r"(a1), "r"(a2), "r"(a3), "r"(b0), "r"(b1));
}

__device__ __forceinline__ void split2(float2 v, uint32_t& h, uint32_t& l) {
    __nv_bfloat162 hp = __floats2bfloat162_rn(v.x, v.y);
    float hx = __low2float(hp), hy = __high2float(hp);
    __nv_bfloat162 lp = __floats2bfloat162_rn(v.x - hx, v.y - hy);
    h = *reinterpret_cast<uint32_t*>(&hp);
    l = *reinterpret_cast<uint32_t*>(&lp);
}

__device__ __forceinline__ void split2h(float2 v, uint32_t& h, uint32_t& l) {
    __half2 hp = __floats2half2_rn(v.x, v.y);
    float hx = __low2float(hp), hy = __high2float(hp);
    __half2 lp = __floats2half2_rn(v.x - hx, v.y - hy);
    h = *reinterpret_cast<uint32_t*>(&hp);
    l = *reinterpret_cast<uint32_t*>(&lp);
}

__device__ __forceinline__ uint32_t hscale(uint32_t u, __half2 s) {
    __half2 v = *reinterpret_cast<__half2*>(&u);
    v = __hmul2(v, s);
    return *reinterpret_cast<uint32_t*>(&v);
}

// ---------------- K0: zero scratch + pack W fragments + bias ----------------
__global__ void k_init(const float* __restrict__ WO, const float* __restrict__ WI,
                       const float* __restrict__ WS, const float* __restrict__ bO,
                       const float* __restrict__ bI, const float* __restrict__ bS) {
    size_t idx = (size_t)blockIdx.x * blockDim.x + threadIdx.x;
    size_t stride = (size_t)gridDim.x * blockDim.x;
    const size_t n4 = (size_t)N_NODES * 16;
    uint4 z = make_uint4(0, 0, 0, 0);
    uint4* ao = reinterpret_cast<uint4*>(g_acc_o);
    uint4* ai = reinterpret_cast<uint4*>(g_acc_i);
    for (size_t i = idx; i < n4; i += stride) { ao[i] = z; ai[i] = z; }
    float4 zf = make_float4(0.f, 0.f, 0.f, 0.f);
    float4* cp = reinterpret_cast<float4*>(g_cnt);
    for (size_t i = idx; i < (2 * N_NODES) / 4; i += stride) cp[i] = zf;
    if (idx < D) { g_sum[idx] = 0.0; g_sumsq[idx] = 0.0; g_bias[idx] = bO[idx] + bI[idx] + bS[idx]; }
    if (idx < 24 * 16 * 32) {
        int t  = (int)idx >> 9;
        int nt = ((int)idx >> 5) & 15;
        int l  = (int)idx & 31;
        int n  = nt * 8 + (l >> 2);
        int kg = t * 16 + (l & 3) * 2;
        const float* Wsrc = (kg < 128) ? WO : ((kg < 256) ? WI : WS);
        int kk = kg & 127;
        float w00 = __ldg(&Wsrc[n * 128 + kk]);
        float w01 = __ldg(&Wsrc[n * 128 + kk + 1]);
        float w10 = __ldg(&Wsrc[n * 128 + kk + 8]);
        float w11 = __ldg(&Wsrc[n * 128 + kk + 9]);
        uint32_t b0h, b0l, b1h, b1l;
        if (t < 16) {
            split2h(make_float2(w00, w01), b0h, b0l);
            split2h(make_float2(w10, w11), b1h, b1l);
        } else {
            split2(make_float2(w00, w01), b0h, b0l);
            split2(make_float2(w10, w11), b1h, b1l);
        }
        g_Bfrag[idx] = make_uint4(b0h, b1h, b0l, b1l);
    }
}

// ---------------- K1: edge scatter (permuted fragment layout) ----------------
__global__ __launch_bounds__(256) void k_scatter(const float* __restrict__ node,
                                                 const float* __restrict__ edge,
                                                 const int* __restrict__ src,
                                                 const int* __restrict__ dst) {
    int e = blockIdx.x * 8 + (threadIdx.x >> 5);
    if (e >= N_EDGES) return;
    int lane = threadIdx.x & 31;
    int half = lane >> 4;
    int i = lane & 15;
    int tp = i >> 2, g = i & 3;
    int s = __ldg(&src[e]);
    int d = __ldg(&dst[e]);
    int nrow = half ? d : s;
    const float2* e2 = reinterpret_cast<const float2*>(edge) + (size_t)e * 64;
    const float2* n2 = reinterpret_cast<const float2*>(node) + (size_t)nrow * 64;
    int base = tp * 16 + g;
    __half2 m[4];
#pragma unroll
    for (int j = 0; j < 4; j++) {
        int ix = base + j * 4;
        float2 nv = __ldg(&n2[ix]);
        float2 ev = __ldg(&e2[ix]);
        m[j] = __floats2half2_rn(nv.x - ev.x, nv.y - ev.y);
    }
    __half2* bp = half ? (g_acc_i + (size_t)s * 64) : (g_acc_o + (size_t)d * 64);
    red_add_h2v4(bp + i * 4, m[0], m[1], m[2], m[3]);
    if (lane == 0)  atomicAdd(&g_cnt[d], 1.f);
    if (lane == 16) atomicAdd(&g_cnt[N_NODES + s], 1.f);
}

// ---------------- K2: HMMA GEMM, B table in smem, 512 threads ----------------
// CTA: 256 rows x 128 cols, 16 warps = 8 (rows, wy) x 2 (cols, wx), warp tile 32x64.
#define GEMM_SMEM (24 * 16 * 32 * 16)   // 196608 B

__global__ __launch_bounds__(512, 1) void k_gemm(const float* __restrict__ node,
                                                 float* __restrict__ out) {
    extern __shared__ uint4 sB[];
    __shared__ float s_inv[2 * 256];
    __shared__ float s_red[2 * 128];

    int tid = threadIdx.x;
    int l = tid & 31;
    int w = tid >> 5;
    int wy = w & 7;           // row group (8 x 32 rows)
    int wx = w >> 3;          // col group
    int row0 = blockIdx.x * 256;

    // stage B table (192KB) into smem
    {
        const uint4* gb = g_Bfrag;
#pragma unroll
        for (int t = 0; t < 24; t++) sB[tid + t * 512] = __ldg(&gb[tid + t * 512]);
    }
    {
        int r = row0 + (tid & 255);
        float v = 0.f;
        if (r < N_NODES) v = 1.f / fmaxf(g_cnt[(tid < 256 ? 0 : N_NODES) + r], 1.f);
        s_inv[tid] = v;
        if (tid < 256) s_red[tid] = 0.f;
    }
    __syncthreads();

    float acc[2][8][4];
#pragma unroll
    for (int mt = 0; mt < 2; mt++)
#pragma unroll
        for (int nt = 0; nt < 8; nt++)
#pragma unroll
            for (int q = 0; q < 4; q++) acc[mt][nt][q] = 0.f;

    const int lq = l >> 2;            // 0..7 row within tile group
    const int gg = l & 3;             // k group
    const int lk = gg * 2;

    int rl0 = wy * 32 + lq;           // mt=0 row a
    int rl1 = rl0 + 16;               // mt=1 row a  (rows +8 are the "b" rows)
    // NOTE: fragment rows are (lq, lq+8) within each 16-row mt tile:
    // mt tile base = wy*32 + mt*16; rows = base+lq, base+lq+8.

    // ---- fp16 sources (permuted layout): sel 0 = acc_o (t 0..7), 1 = acc_i (t 8..15) ----
#pragma unroll
    for (int sel = 0; sel < 2; sel++) {
        const uint4* hb = reinterpret_cast<const uint4*>(sel ? g_acc_i : g_acc_o);
        // per-row fp16 scales
        __half2 sc[2][2];
#pragma unroll
        for (int mt = 0; mt < 2; mt++) {
            int base = wy * 32 + mt * 16 + lq;
            sc[mt][0] = __float2half2_rn(sel ? s_inv[256 + base] : s_inv[base]);
            sc[mt][1] = __float2half2_rn(sel ? s_inv[256 + base + 8] : s_inv[base + 8]);
        }
#pragma unroll
        for (int tp = 0; tp < 4; tp++) {
            uint32_t A0[2][4], A1[2][4];
#pragma unroll
            for (int mt = 0; mt < 2; mt++) {
                int ga = row0 + wy * 32 + mt * 16 + lq;
                int gb_ = ga + 8;
                uint4 z4 = make_uint4(0, 0, 0, 0);
                uint4 Ua = (ga < N_NODES) ? __ldg(&hb[(size_t)ga * 16 + tp * 4 + gg]) : z4;
                uint4 Ub = (gb_ < N_NODES) ? __ldg(&hb[(size_t)gb_ * 16 + tp * 4 + gg]) : z4;
                Ua.x = hscale(Ua.x, sc[mt][0]); Ua.y = hscale(Ua.y, sc[mt][0]);
                Ua.z = hscale(Ua.z, sc[mt][0]); Ua.w = hscale(Ua.w, sc[mt][0]);
                Ub.x = hscale(Ub.x, sc[mt][1]); Ub.y = hscale(Ub.y, sc[mt][1]);
                Ub.z = hscale(Ub.z, sc[mt][1]); Ub.w = hscale(Ub.w, sc[mt][1]);
                A0[mt][0] = Ua.x; A0[mt][1] = Ub.x; A0[mt][2] = Ua.y; A0[mt][3] = Ub.y;
                A1[mt][0] = Ua.z; A1[mt][1] = Ub.z; A1[mt][2] = Ua.w; A1[mt][3] = Ub.w;
            }
#pragma unroll
            for (int sub = 0; sub < 2; sub++) {
                int t = sel * 8 + tp * 2 + sub;
                const uint4* sBt = sB + (t * 16 + wx * 8) * 32 + l;
#pragma unroll
                for (int nt = 0; nt < 8; nt++) {
                    uint4 B = sBt[nt * 32];
#pragma unroll
                    for (int mt = 0; mt < 2; mt++) {
                        uint32_t* A = sub ? A1[mt] : A0[mt];
                        mma_fp16(acc[mt][nt], A[0], A[1], A[2], A[3], B.x, B.y);
                        mma_fp16(acc[mt][nt], A[0], A[1], A[2], A[3], B.z, B.w);
                    }
                }
            }
        }
    }

    // ---- bf16 source: node embeddings (t 16..23), on-the-fly split ----
#pragma unroll 2
    for (int t = 16; t < 24; t++) {
        int koff = ((t - 16) * 16 + lk) >> 1;   // float2 index within row
        uint32_t aH[2][4], aL[2][4];
#pragma unroll
        for (int mt = 0; mt < 2; mt++) {
            int ga = row0 + wy * 32 + mt * 16 + lq;
            int gb_ = ga + 8;
            const float2* b2 = reinterpret_cast<const float2*>(node);
            float2 zz = make_float2(0.f, 0.f);
            float2 p00 = (ga < N_NODES) ? __ldg(&b2[(size_t)ga * 64 + koff]) : zz;
            float2 p01 = (ga < N_NODES) ? __ldg(&b2[(size_t)ga * 64 + koff + 4]) : zz;
            float2 p10 = (gb_ < N_NODES) ? __ldg(&b2[(size_t)gb_ * 64 + koff]) : zz;
            float2 p11 = (gb_ < N_NODES) ? __ldg(&b2[(size_t)gb_ * 64 + koff + 4]) : zz;
            split2(p00, aH[mt][0], aL[mt][0]);
            split2(p10, aH[mt][1], aL[mt][1]);
            split2(p01, aH[mt][2], aL[mt][2]);
            split2(p11, aH[mt][3], aL[mt][3]);
        }
        const uint4* sBt = sB + (t * 16 + wx * 8) * 32 + l;
#pragma unroll
        for (int nt = 0; nt < 8; nt++) {
            uint4 B = sBt[nt * 32];
#pragma unroll
            for (int mt = 0; mt < 2; mt++) {
                mma_bf(acc[mt][nt], aH[mt][0], aH[mt][1], aH[mt][2], aH[mt][3], B.x, B.y);
                mma_bf(acc[mt][nt], aH[mt][0], aH[mt][1], aH[mt][2], aH[mt][3], B.z, B.w);
                mma_bf(acc[mt][nt], aL[mt][0], aL[mt][1], aL[mt][2], aL[mt][3], B.x, B.y);
            }
        }
    }

    // ---- epilogue: h = (acc + bias)/3, store, BN partial stats ----
    const float third = 1.f / 3.f;
    const float2* bias2 = reinterpret_cast<const float2*>(g_bias);
    float2* o2 = reinterpret_cast<float2*>(out);
    float ps[16], pq[16];
#pragma unroll
    for (int j = 0; j < 16; j++) { ps[j] = 0.f; pq[j] = 0.f; }

#pragma unroll
    for (int mt = 0; mt < 2; mt++) {
        int ra = row0 + wy * 32 + mt * 16 + lq;
        int rb = ra + 8;
#pragma unroll
        for (int nt = 0; nt < 8; nt++) {
            int col = wx * 64 + nt * 8 + lk;
            float2 bv = __ldg(&bias2[col >> 1]);
            if (ra < N_NODES) {
                float2 h0;
                h0.x = (acc[mt][nt][0] + bv.x) * third;
                h0.y = (acc[mt][nt][1] + bv.y) * third;
                o2[(size_t)ra * 64 + (col >> 1)] = h0;
                ps[nt * 2 + 0] += h0.x; pq[nt * 2 + 0] += h0.x * h0.x;
                ps[nt * 2 + 1] += h0.y; pq[nt * 2 + 1] += h0.y * h0.y;
            }
            if (rb < N_NODES) {
                float2 h1;
                h1.x = (acc[mt][nt][2] + bv.x) * third;
                h1.y = (acc[mt][nt][3] + bv.y) * third;
                o2[(size_t)rb * 64 + (col >> 1)] = h1;
                ps[nt * 2 + 0] += h1.x; pq[nt * 2 + 0] += h1.x * h1.x;
                ps[nt * 2 + 1] += h1.y; pq[nt * 2 + 1] += h1.y * h1.y;
            }
        }
    }
#pragma unroll
    for (int j = 0; j < 16; j++) {
        ps[j] += __shfl_xor_sync(0xFFFFFFFFu, ps[j], 4);
        ps[j] += __shfl_xor_sync(0xFFFFFFFFu, ps[j], 8);
        ps[j] += __shfl_xor_sync(0xFFFFFFFFu, ps[j], 16);
        pq[j] += __shfl_xor_sync(0xFFFFFFFFu, pq[j], 4);
        pq[j] += __shfl_xor_sync(0xFFFFFFFFu, pq[j], 8);
        pq[j] += __shfl_xor_sync(0xFFFFFFFFu, pq[j], 16);
    }
    if (l < 4) {
#pragma unroll
        for (int j = 0; j < 16; j++) {
            int col = wx * 64 + (j >> 1) * 8 + l * 2 + (j & 1);
            atomicAdd(&s_red[col], ps[j]);
            atomicAdd(&s_red[128 + col], pq[j]);
        }
    }
    __syncthreads();
    if (tid < 128)      atomicAdd(&g_sum[tid], (double)s_red[tid]);
    else if (tid < 256) atomicAdd(&g_sumsq[tid - 128], (double)s_red[tid]);
}

// ---------------- K3: finalize BN affine ----------------
__global__ void k_finalize(const float* __restrict__ gamma, const float* __restrict__ beta) {
    int j = threadIdx.x;
    double mu = g_sum[j] / (double)N_NODES;
    double var = g_sumsq[j] / (double)N_NODES - mu * mu;
    float sc = gamma[j] * rsqrtf((float)var + BN_EPS);
    g_scale[j] = sc;
    g_shift[j] = beta[j] - (float)mu * sc;
}

// ---------------- K4: in-place normalize ----------------
__global__ void k_bn(float* __restrict__ out) {
    size_t idx = (size_t)blockIdx.x * blockDim.x + threadIdx.x;
    size_t stride = (size_t)gridDim.x * blockDim.x;
    const size_t n4 = (size_t)N_NODES * D / 4;
    float4* o4 = reinterpret_cast<float4*>(out);
    const float4* sc4 = reinterpret_cast<const float4*>(g_scale);
    const float4* sh4 = reinterpret_cast<const float4*>(g_shift);
    for (size_t i = idx; i < n4; i += stride) {
        float4 sc = sc4[i & 31];
        float4 sh = sh4[i & 31];
        float4 v = o4[i];
        v.x = fmaf(v.x, sc.x, sh.x);
        v.y = fmaf(v.y, sc.y, sh.y);
        v.z = fmaf(v.z, sc.z, sh.z);
        v.w = fmaf(v.w, sc.w, sh.w);
        o4[i] = v;
    }
}

// ---------------- launch ----------------
extern "C" void kernel_launch(void* const* d_in, const int* in_sizes, int n_in,
                              void* d_out, int out_size) {
    const float* node  = (const float*)d_in[0];
    const float* edge  = (const float*)d_in[1];
    const float* WO    = (const float*)d_in[2];
    const float* bO    = (const float*)d_in[3];
    const float* WI    = (const float*)d_in[4];
    const float* bI    = (const float*)d_in[5];
    const float* WS    = (const float*)d_in[6];
    const float* bS    = (const float*)d_in[7];
    const float* gamma = (const float*)d_in[8];
    const float* beta  = (const float*)d_in[9];
    const int*   src   = (const int*)d_in[10];
    const int*   dst   = (const int*)d_in[11];
    float* out = (float*)d_out;

    cudaFuncSetAttribute(k_gemm, cudaFuncAttributeMaxDynamicSharedMemorySize, GEMM_SMEM);

    k_init<<<1184, 256>>>(WO, WI, WS, bO, bI, bS);
    k_scatter<<<N_EDGES / 8, 256>>>(node, edge, src, dst);
    k_gemm<<<(N_NODES + 255) / 256, 512, GEMM_SMEM>>>(node, out);
    k_finalize<<<1, 128>>>(gamma, beta);
    k_bn<<<2048, 256>>>(out);
}

// round 8
// speedup vs baseline: 1.0050x; 1.0050x over previous
#include <cuda_runtime.h>
#include <cuda_bf16.h>
#include <cuda_fp16.h>
#include <cstdint>
#include <cstddef>

#define N_NODES 100000
#define N_EDGES 600000
#define D 128
#define BN_EPS 1e-5f

// ---------------- scratch (static device globals; no allocation) ----------------
// Accumulators in PERMUTED fragment layout (fp16). Per row: 16 uint4; uint4 index
// u = tp*4 + g (tp=0..3 kstep-pair, g=0..3 lane-k-group). Halves within uint4:
// [t=2tp: K=32tp+2g,+1 | +8,+9 | t=2tp+1: K=32tp+16+2g,+1 | +8,+9]
__device__ __half2 g_acc_o[(size_t)N_NODES * 64];
__device__ __half2 g_acc_i[(size_t)N_NODES * 64];
__device__ float  g_cnt[2 * N_NODES];               // [0:N) in-deg(dst), [N:2N) deg at src
// B fragments: [kstep 0..23][ntile 0..15][lane 0..31] = (b0h,b1h,b0l,b1l)
// ksteps 0..15: fp16 hi/lo split;  ksteps 16..23: bf16 hi/lo split
__device__ uint4  g_Bfrag[24 * 16 * 32];
__device__ float  g_bias[D];
__device__ double g_sum[D];
__device__ double g_sumsq[D];
__device__ float  g_scale[D];
__device__ float  g_shift[D];

// ---------------- helpers ----------------
__device__ __forceinline__ void red_add_h2v4(__half2* p, __half2 a, __half2 b,
                                             __half2 c, __half2 d) {
    asm volatile("red.global.add.noftz.v4.f16x2 [%0], {%1,%2,%3,%4};"
                 :: "l"(p),
                    "r"(*reinterpret_cast<uint32_t*>(&a)),
                    "r"(*reinterpret_cast<uint32_t*>(&b)),
                    "r"(*reinterpret_cast<uint32_t*>(&c)),
                    "r"(*reinterpret_cast<uint32_t*>(&d)) : "memory");
}

__device__ __forceinline__ void mma_bf(float* d, uint32_t a0, uint32_t a1, uint32_t a2,
                                       uint32_t a3, uint32_t b0, uint32_t b1) {
    asm volatile(
        "mma.sync.aligned.m16n8k16.row.col.f32.bf16.bf16.f32 "
        "{%0,%1,%2,%3}, {%4,%5,%6,%7}, {%8,%9}, {%0,%1,%2,%3};"
        : "+f"(d[0]), "+f"(d[1]), "+f"(d[2]), "+f"(d[3])
        : "r"(a0), "r"(a1), "r"(a2), "r"(a3), "r"(b0), "r"(b1));
}

__device__ __forceinline__ void mma_fp16(float* d, uint32_t a0, uint32_t a1, uint32_t a2,
                                         uint32_t a3, uint32_t b0, uint32_t b1) {
    asm volatile(
        "mma.sync.aligned.m16n8k16.row.col.f32.f16.f16.f32 "
        "{%0,%1,%2,%3}, {%4,%5,%6,%7}, {%8,%9}, {%0,%1,%2,%3};"
        : "+f"(d[0]), "+f"(d[1]), "+f"(d[2]), "+f"(d[3])
        : "r"(a0), "r"(a1), "r"(a2), "r"(a3), "r"(b0), "r"(b1));
}

__device__ __forceinline__ void split2(float2 v, uint32_t& h, uint32_t& l) {
    __nv_bfloat162 hp = __floats2bfloat162_rn(v.x, v.y);
    float hx = __low2float(hp), hy = __high2float(hp);
    __nv_bfloat162 lp = __floats2bfloat162_rn(v.x - hx, v.y - hy);
    h = *reinterpret_cast<uint32_t*>(&hp);
    l = *reinterpret_cast<uint32_t*>(&lp);
}

__device__ __forceinline__ void split2h(float2 v, uint32_t& h, uint32_t& l) {
    __half2 hp = __floats2half2_rn(v.x, v.y);
    float hx = __low2float(hp), hy = __high2float(hp);
    __half2 lp = __floats2half2_rn(v.x - hx, v.y - hy);
    h = *reinterpret_cast<uint32_t*>(&hp);
    l = *reinterpret_cast<uint32_t*>(&lp);
}

__device__ __forceinline__ uint32_t hscale(uint32_t u, __half2 s) {
    __half2 v = *reinterpret_cast<__half2*>(&u);
    v = __hmul2(v, s);
    return *reinterpret_cast<uint32_t*>(&v);
}

// ---------------- K0: zero scratch + pack W fragments + bias ----------------
__global__ void k_init(const float* __restrict__ WO, const float* __restrict__ WI,
                       const float* __restrict__ WS, const float* __restrict__ bO,
                       const float* __restrict__ bI, const float* __restrict__ bS) {
    size_t idx = (size_t)blockIdx.x * blockDim.x + threadIdx.x;
    size_t stride = (size_t)gridDim.x * blockDim.x;
    const size_t n4 = (size_t)N_NODES * 16;
    uint4 z = make_uint4(0, 0, 0, 0);
    uint4* ao = reinterpret_cast<uint4*>(g_acc_o);
    uint4* ai = reinterpret_cast<uint4*>(g_acc_i);
    for (size_t i = idx; i < n4; i += stride) { ao[i] = z; ai[i] = z; }
    float4 zf = make_float4(0.f, 0.f, 0.f, 0.f);
    float4* cp = reinterpret_cast<float4*>(g_cnt);
    for (size_t i = idx; i < (2 * N_NODES) / 4; i += stride) cp[i] = zf;
    if (idx < D) { g_sum[idx] = 0.0; g_sumsq[idx] = 0.0; g_bias[idx] = bO[idx] + bI[idx] + bS[idx]; }
    if (idx < 24 * 16 * 32) {
        int t  = (int)idx >> 9;
        int nt = ((int)idx >> 5) & 15;
        int l  = (int)idx & 31;
        int n  = nt * 8 + (l >> 2);
        int kg = t * 16 + (l & 3) * 2;
        const float* Wsrc = (kg < 128) ? WO : ((kg < 256) ? WI : WS);
        int kk = kg & 127;
        float w00 = __ldg(&Wsrc[n * 128 + kk]);
        float w01 = __ldg(&Wsrc[n * 128 + kk + 1]);
        float w10 = __ldg(&Wsrc[n * 128 + kk + 8]);
        float w11 = __ldg(&Wsrc[n * 128 + kk + 9]);
        uint32_t b0h, b0l, b1h, b1l;
        if (t < 16) {
            split2h(make_float2(w00, w01), b0h, b0l);
            split2h(make_float2(w10, w11), b1h, b1l);
        } else {
            split2(make_float2(w00, w01), b0h, b0l);
            split2(make_float2(w10, w11), b1h, b1l);
        }
        g_Bfrag[idx] = make_uint4(b0h, b1h, b0l, b1l);
    }
}

// ---------------- K1: edge scatter (permuted fragment layout) ----------------
__global__ __launch_bounds__(256) void k_scatter(const float* __restrict__ node,
                                                 const float* __restrict__ edge,
                                                 const int* __restrict__ src,
                                                 const int* __restrict__ dst) {
    int e = blockIdx.x * 8 + (threadIdx.x >> 5);
    if (e >= N_EDGES) return;
    int lane = threadIdx.x & 31;
    int half = lane >> 4;
    int i = lane & 15;
    int tp = i >> 2, g = i & 3;
    int s = __ldg(&src[e]);
    int d = __ldg(&dst[e]);
    int nrow = half ? d : s;
    const float2* e2 = reinterpret_cast<const float2*>(edge) + (size_t)e * 64;
    const float2* n2 = reinterpret_cast<const float2*>(node) + (size_t)nrow * 64;
    int base = tp * 16 + g;
    __half2 m[4];
#pragma unroll
    for (int j = 0; j < 4; j++) {
        int ix = base + j * 4;
        float2 nv = __ldg(&n2[ix]);
        float2 ev = __ldg(&e2[ix]);
        m[j] = __floats2half2_rn(nv.x - ev.x, nv.y - ev.y);
    }
    __half2* bp = half ? (g_acc_i + (size_t)s * 64) : (g_acc_o + (size_t)d * 64);
    red_add_h2v4(bp + i * 4, m[0], m[1], m[2], m[3]);
    if (lane == 0)  atomicAdd(&g_cnt[d], 1.f);
    if (lane == 16) atomicAdd(&g_cnt[N_NODES + s], 1.f);
}

// ---------------- K2: HMMA GEMM (256 thr, 2 CTA/SM, permuted A loads) ----------------
// CTA: 128 rows x 128 cols, 8 warps = 4 (rows, wy) x 2 (cols, wx), warp tile 32x64.
__global__ __launch_bounds__(256, 2) void k_gemm(const float* __restrict__ node,
                                                 float* __restrict__ out) {
    __shared__ float s_inv[2 * 128];
    __shared__ float s_red[2 * 128];

    int tid = threadIdx.x;
    int l = tid & 31;
    int w = tid >> 5;
    int wy = w & 3;           // row group
    int wx = w >> 2;          // col group
    int row0 = blockIdx.x * 128;

    {
        int i = tid & 127;
        int r = row0 + i;
        float v = 0.f;
        if (r < N_NODES) v = 1.f / fmaxf(g_cnt[(tid < 128 ? 0 : N_NODES) + r], 1.f);
        s_inv[tid] = v;
        if (tid < 128) { s_red[tid] = 0.f; s_red[128 + tid] = 0.f; }
    }
    __syncthreads();

    float acc[2][8][4];
#pragma unroll
    for (int mt = 0; mt < 2; mt++)
#pragma unroll
        for (int nt = 0; nt < 8; nt++)
#pragma unroll
            for (int q = 0; q < 4; q++) acc[mt][nt][q] = 0.f;

    const int lq = l >> 2;            // 0..7 row within tile group
    const int gg = l & 3;             // k group
    const int lk = gg * 2;

    // global row indices for the 4 fragment rows this lane touches
    int ga0 = row0 + wy * 32 + lq;          // mt=0 row a
    int gb0 = ga0 + 8;                      // mt=0 row b
    int ga1 = ga0 + 16;                     // mt=1 row a
    int gb1 = ga0 + 24;                     // mt=1 row b
    bool va0 = ga0 < N_NODES, vb0 = gb0 < N_NODES, va1 = ga1 < N_NODES, vb1 = gb1 < N_NODES;

    // ---- fp16 sources (permuted layout): sel 0 = acc_o (t 0..7), 1 = acc_i (t 8..15) ----
#pragma unroll
    for (int sel = 0; sel < 2; sel++) {
        const uint4* hb = reinterpret_cast<const uint4*>(sel ? g_acc_i : g_acc_o);
        __half2 sc[2][2];
#pragma unroll
        for (int mt = 0; mt < 2; mt++) {
            int base = wy * 32 + mt * 16 + lq;
            sc[mt][0] = __float2half2_rn(sel ? s_inv[128 + base] : s_inv[base]);
            sc[mt][1] = __float2half2_rn(sel ? s_inv[128 + base + 8] : s_inv[base + 8]);
        }
        uint4 z4 = make_uint4(0, 0, 0, 0);
        // prefetch tp = 0
        uint4 U[4];
        U[0] = va0 ? __ldg(&hb[(size_t)ga0 * 16 + gg]) : z4;
        U[1] = vb0 ? __ldg(&hb[(size_t)gb0 * 16 + gg]) : z4;
        U[2] = va1 ? __ldg(&hb[(size_t)ga1 * 16 + gg]) : z4;
        U[3] = vb1 ? __ldg(&hb[(size_t)gb1 * 16 + gg]) : z4;
#pragma unroll
        for (int tp = 0; tp < 4; tp++) {
            uint4 Un[4];
            if (tp < 3) {
                int o = (tp + 1) * 4 + gg;
                Un[0] = va0 ? __ldg(&hb[(size_t)ga0 * 16 + o]) : z4;
                Un[1] = vb0 ? __ldg(&hb[(size_t)gb0 * 16 + o]) : z4;
                Un[2] = va1 ? __ldg(&hb[(size_t)ga1 * 16 + o]) : z4;
                Un[3] = vb1 ? __ldg(&hb[(size_t)gb1 * 16 + o]) : z4;
            }
            uint32_t A0[2][4], A1[2][4];
#pragma unroll
            for (int mt = 0; mt < 2; mt++) {
                uint4 Ua = U[mt * 2], Ub = U[mt * 2 + 1];
                A0[mt][0] = hscale(Ua.x, sc[mt][0]); A0[mt][1] = hscale(Ub.x, sc[mt][1]);
                A0[mt][2] = hscale(Ua.y, sc[mt][0]); A0[mt][3] = hscale(Ub.y, sc[mt][1]);
                A1[mt][0] = hscale(Ua.z, sc[mt][0]); A1[mt][1] = hscale(Ub.z, sc[mt][1]);
                A1[mt][2] = hscale(Ua.w, sc[mt][0]); A1[mt][3] = hscale(Ub.w, sc[mt][1]);
            }
#pragma unroll
            for (int sub = 0; sub < 2; sub++) {
                int t = sel * 8 + tp * 2 + sub;
                const uint4* gBt = g_Bfrag + (t * 16 + wx * 8) * 32 + l;
#pragma unroll
                for (int nt = 0; nt < 8; nt++) {
                    uint4 B = __ldg(&gBt[nt * 32]);
#pragma unroll
                    for (int mt = 0; mt < 2; mt++) {
                        uint32_t* A = sub ? A1[mt] : A0[mt];
                        mma_fp16(acc[mt][nt], A[0], A[1], A[2], A[3], B.x, B.y);
                        mma_fp16(acc[mt][nt], A[0], A[1], A[2], A[3], B.z, B.w);
                    }
                }
            }
            U[0] = Un[0]; U[1] = Un[1]; U[2] = Un[2]; U[3] = Un[3];
        }
    }

    // ---- bf16 source: node embeddings (t 16..23), on-the-fly split ----
#pragma unroll 2
    for (int t = 16; t < 24; t++) {
        int koff = ((t - 16) * 16 + lk) >> 1;
        uint32_t aH[2][4], aL[2][4];
#pragma unroll
        for (int mt = 0; mt < 2; mt++) {
            int ga = (mt == 0) ? ga0 : ga1;
            int gb_ = (mt == 0) ? gb0 : gb1;
            const float2* b2 = reinterpret_cast<const float2*>(node);
            float2 zz = make_float2(0.f, 0.f);
            float2 p00 = (ga < N_NODES) ? __ldg(&b2[(size_t)ga * 64 + koff]) : zz;
            float2 p01 = (ga < N_NODES) ? __ldg(&b2[(size_t)ga * 64 + koff + 4]) : zz;
            float2 p10 = (gb_ < N_NODES) ? __ldg(&b2[(size_t)gb_ * 64 + koff]) : zz;
            float2 p11 = (gb_ < N_NODES) ? __ldg(&b2[(size_t)gb_ * 64 + koff + 4]) : zz;
            split2(p00, aH[mt][0], aL[mt][0]);
            split2(p10, aH[mt][1], aL[mt][1]);
            split2(p01, aH[mt][2], aL[mt][2]);
            split2(p11, aH[mt][3], aL[mt][3]);
        }
        const uint4* gBt = g_Bfrag + (t * 16 + wx * 8) * 32 + l;
#pragma unroll
        for (int nt = 0; nt < 8; nt++) {
            uint4 B = __ldg(&gBt[nt * 32]);
#pragma unroll
            for (int mt = 0; mt < 2; mt++) {
                mma_bf(acc[mt][nt], aH[mt][0], aH[mt][1], aH[mt][2], aH[mt][3], B.x, B.y);
                mma_bf(acc[mt][nt], aH[mt][0], aH[mt][1], aH[mt][2], aH[mt][3], B.z, B.w);
                mma_bf(acc[mt][nt], aL[mt][0], aL[mt][1], aL[mt][2], aL[mt][3], B.x, B.y);
            }
        }
    }

    // ---- epilogue: h = (acc + bias)/3, store, BN partial stats ----
    const float third = 1.f / 3.f;
    const float2* bias2 = reinterpret_cast<const float2*>(g_bias);
    float2* o2 = reinterpret_cast<float2*>(out);
    float ps[16], pq[16];
#pragma unroll
    for (int j = 0; j < 16; j++) { ps[j] = 0.f; pq[j] = 0.f; }

#pragma unroll
    for (int mt = 0; mt < 2; mt++) {
        int ra = (mt == 0) ? ga0 : ga1;
        int rb = (mt == 0) ? gb0 : gb1;
#pragma unroll
        for (int nt = 0; nt < 8; nt++) {
            int col = wx * 64 + nt * 8 + lk;
            float2 bv = __ldg(&bias2[col >> 1]);
            if (ra < N_NODES) {
                float2 h0;
                h0.x = (acc[mt][nt][0] + bv.x) * third;
                h0.y = (acc[mt][nt][1] + bv.y) * third;
                o2[(size_t)ra * 64 + (col >> 1)] = h0;
                ps[nt * 2 + 0] += h0.x; pq[nt * 2 + 0] += h0.x * h0.x;
                ps[nt * 2 + 1] += h0.y; pq[nt * 2 + 1] += h0.y * h0.y;
            }
            if (rb < N_NODES) {
                float2 h1;
                h1.x = (acc[mt][nt][2] + bv.x) * third;
                h1.y = (acc[mt][nt][3] + bv.y) * third;
                o2[(size_t)rb * 64 + (col >> 1)] = h1;
                ps[nt * 2 + 0] += h1.x; pq[nt * 2 + 0] += h1.x * h1.x;
                ps[nt * 2 + 1] += h1.y; pq[nt * 2 + 1] += h1.y * h1.y;
            }
        }
    }
#pragma unroll
    for (int j = 0; j < 16; j++) {
        ps[j] += __shfl_xor_sync(0xFFFFFFFFu, ps[j], 4);
        ps[j] += __shfl_xor_sync(0xFFFFFFFFu, ps[j], 8);
        ps[j] += __shfl_xor_sync(0xFFFFFFFFu, ps[j], 16);
        pq[j] += __shfl_xor_sync(0xFFFFFFFFu, pq[j], 4);
        pq[j] += __shfl_xor_sync(0xFFFFFFFFu, pq[j], 8);
        pq[j] += __shfl_xor_sync(0xFFFFFFFFu, pq[j], 16);
    }
    if (l < 4) {
#pragma unroll
        for (int j = 0; j < 16; j++) {
            int col = wx * 64 + (j >> 1) * 8 + l * 2 + (j & 1);
            atomicAdd(&s_red[col], ps[j]);
            atomicAdd(&s_red[128 + col], pq[j]);
        }
    }
    __syncthreads();
    if (tid < 128) atomicAdd(&g_sum[tid], (double)s_red[tid]);
    else           atomicAdd(&g_sumsq[tid - 128], (double)s_red[tid]);
}

// ---------------- K3: finalize BN affine ----------------
__global__ void k_finalize(const float* __restrict__ gamma, const float* __restrict__ beta) {
    int j = threadIdx.x;
    double mu = g_sum[j] / (double)N_NODES;
    double var = g_sumsq[j] / (double)N_NODES - mu * mu;
    float sc = gamma[j] * rsqrtf((float)var + BN_EPS);
    g_scale[j] = sc;
    g_shift[j] = beta[j] - (float)mu * sc;
}

// ---------------- K4: in-place normalize ----------------
__global__ void k_bn(float* __restrict__ out) {
    size_t idx = (size_t)blockIdx.x * blockDim.x + threadIdx.x;
    size_t stride = (size_t)gridDim.x * blockDim.x;
    const size_t n4 = (size_t)N_NODES * D / 4;
    float4* o4 = reinterpret_cast<float4*>(out);
    const float4* sc4 = reinterpret_cast<const float4*>(g_scale);
    const float4* sh4 = reinterpret_cast<const float4*>(g_shift);
    for (size_t i = idx; i < n4; i += stride) {
        float4 sc = sc4[i & 31];
        float4 sh = sh4[i & 31];
        float4 v = o4[i];
        v.x = fmaf(v.x, sc.x, sh.x);
        v.y = fmaf(v.y, sc.y, sh.y);
        v.z = fmaf(v.z, sc.z, sh.z);
        v.w = fmaf(v.w, sc.w, sh.w);
        o4[i] = v;
    }
}

// ---------------- launch ----------------
extern "C" void kernel_launch(void* const* d_in, const int* in_sizes, int n_in,
                              void* d_out, int out_size) {
    const float* node  = (const float*)d_in[0];
    const float* edge  = (const float*)d_in[1];
    const float* WO    = (const float*)d_in[2];
    const float* bO    = (const float*)d_in[3];
    const float* WI    = (const float*)d_in[4];
    const float* bI    = (const float*)d_in[5];
    const float* WS    = (const float*)d_in[6];
    const float* bS    = (const float*)d_in[7];
    const float* gamma = (const float*)d_in[8];
    const float* beta  = (const float*)d_in[9];
    const int*   src   = (const int*)d_in[10];
    const int*   dst   = (const int*)d_in[11];
    float* out = (float*)d_out;

    k_init<<<1184, 256>>>(WO, WI, WS, bO, bI, bS);
    k_scatter<<<N_EDGES / 8, 256>>>(node, edge, src, dst);
    k_gemm<<<(N_NODES + 127) / 128, 256>>>(node, out);
    k_finalize<<<1, 128>>>(gamma, beta);
    k_bn<<<2048, 256>>>(out);
}

// round 9
// speedup vs baseline: 1.1780x; 1.1721x over previous
#include <cuda_runtime.h>
#include <cuda_bf16.h>
#include <cuda_fp16.h>
#include <cstdint>
#include <cstddef>

#define N_NODES 100000
#define N_EDGES 600000
#define D 128
#define BN_EPS 1e-5f

// ---------------- scratch (static device globals; no allocation) ----------------
// LINEAR layout fp16 accumulators: row-major, 128 cols per row (256B/row)
__device__ __half2 g_acc_o[(size_t)N_NODES * 64];
__device__ __half2 g_acc_i[(size_t)N_NODES * 64];
__device__ float  g_cnt[2 * N_NODES];               // [0:N) in-deg(dst), [N:2N) deg at src
// B fragments: [kstep 0..23][ntile 0..15][lane 0..31] = (b0h,b1h,b0l,b1l)
// ksteps 0..15: fp16 hi/lo split;  ksteps 16..23: bf16 hi/lo split
__device__ uint4  g_Bfrag[24 * 16 * 32];
__device__ float  g_bias[D];
__device__ double g_sum[D];
__device__ double g_sumsq[D];

// ---------------- helpers ----------------
__device__ __forceinline__ void red_add_h2v4(__half2* p, __half2 a, __half2 b,
                                             __half2 c, __half2 d) {
    asm volatile("red.global.add.noftz.v4.f16x2 [%0], {%1,%2,%3,%4};"
                 :: "l"(p),
                    "r"(*reinterpret_cast<uint32_t*>(&a)),
                    "r"(*reinterpret_cast<uint32_t*>(&b)),
                    "r"(*reinterpret_cast<uint32_t*>(&c)),
                    "r"(*reinterpret_cast<uint32_t*>(&d)) : "memory");
}

__device__ __forceinline__ void mma_bf(float* d, uint32_t a0, uint32_t a1, uint32_t a2,
                                       uint32_t a3, uint32_t b0, uint32_t b1) {
    asm volatile(
        "mma.sync.aligned.m16n8k16.row.col.f32.bf16.bf16.f32 "
        "{%0,%1,%2,%3}, {%4,%5,%6,%7}, {%8,%9}, {%0,%1,%2,%3};"
        : "+f"(d[0]), "+f"(d[1]), "+f"(d[2]), "+f"(d[3])
        : "r"(a0), "r"(a1), "r"(a2), "r"(a3), "r"(b0), "r"(b1));
}

__device__ __forceinline__ void mma_fp16(float* d, uint32_t a0, uint32_t a1, uint32_t a2,
                                         uint32_t a3, uint32_t b0, uint32_t b1) {
    asm volatile(
        "mma.sync.aligned.m16n8k16.row.col.f32.f16.f16.f32 "
        "{%0,%1,%2,%3}, {%4,%5,%6,%7}, {%8,%9}, {%0,%1,%2,%3};"
        : "+f"(d[0]), "+f"(d[1]), "+f"(d[2]), "+f"(d[3])
        : "r"(a0), "r"(a1), "r"(a2), "r"(a3), "r"(b0), "r"(b1));
}

__device__ __forceinline__ void split2(float2 v, uint32_t& h, uint32_t& l) {
    __nv_bfloat162 hp = __floats2bfloat162_rn(v.x, v.y);
    float hx = __low2float(hp), hy = __high2float(hp);
    __nv_bfloat162 lp = __floats2bfloat162_rn(v.x - hx, v.y - hy);
    h = *reinterpret_cast<uint32_t*>(&hp);
    l = *reinterpret_cast<uint32_t*>(&lp);
}

__device__ __forceinline__ void split2h(float2 v, uint32_t& h, uint32_t& l) {
    __half2 hp = __floats2half2_rn(v.x, v.y);
    float hx = __low2float(hp), hy = __high2float(hp);
    __half2 lp = __floats2half2_rn(v.x - hx, v.y - hy);
    h = *reinterpret_cast<uint32_t*>(&hp);
    l = *reinterpret_cast<uint32_t*>(&lp);
}

__device__ __forceinline__ uint32_t hscale(uint32_t u, __half2 s) {
    __half2 v = *reinterpret_cast<__half2*>(&u);
    v = __hmul2(v, s);
    return *reinterpret_cast<uint32_t*>(&v);
}

// ---------------- K0: zero scratch + pack W fragments + bias ----------------
__global__ void k_init(const float* __restrict__ WO, const float* __restrict__ WI,
                       const float* __restrict__ WS, const float* __restrict__ bO,
                       const float* __restrict__ bI, const float* __restrict__ bS) {
    size_t idx = (size_t)blockIdx.x * blockDim.x + threadIdx.x;
    size_t stride = (size_t)gridDim.x * blockDim.x;
    const size_t n4 = (size_t)N_NODES * 16;
    uint4 z = make_uint4(0, 0, 0, 0);
    uint4* ao = reinterpret_cast<uint4*>(g_acc_o);
    uint4* ai = reinterpret_cast<uint4*>(g_acc_i);
    for (size_t i = idx; i < n4; i += stride) { ao[i] = z; ai[i] = z; }
    float4 zf = make_float4(0.f, 0.f, 0.f, 0.f);
    float4* cp = reinterpret_cast<float4*>(g_cnt);
    for (size_t i = idx; i < (2 * N_NODES) / 4; i += stride) cp[i] = zf;
    if (idx < D) { g_sum[idx] = 0.0; g_sumsq[idx] = 0.0; g_bias[idx] = bO[idx] + bI[idx] + bS[idx]; }
    if (idx < 24 * 16 * 32) {
        int t  = (int)idx >> 9;
        int nt = ((int)idx >> 5) & 15;
        int l  = (int)idx & 31;
        int n  = nt * 8 + (l >> 2);
        int kg = t * 16 + (l & 3) * 2;
        const float* Wsrc = (kg < 128) ? WO : ((kg < 256) ? WI : WS);
        int kk = kg & 127;
        float w00 = __ldg(&Wsrc[n * 128 + kk]);
        float w01 = __ldg(&Wsrc[n * 128 + kk + 1]);
        float w10 = __ldg(&Wsrc[n * 128 + kk + 8]);
        float w11 = __ldg(&Wsrc[n * 128 + kk + 9]);
        uint32_t b0h, b0l, b1h, b1l;
        if (t < 16) {
            split2h(make_float2(w00, w01), b0h, b0l);
            split2h(make_float2(w10, w11), b1h, b1l);
        } else {
            split2(make_float2(w00, w01), b0h, b0l);
            split2(make_float2(w10, w11), b1h, b1l);
        }
        g_Bfrag[idx] = make_uint4(b0h, b1h, b0l, b1l);
    }
}

// ---------------- K1: edge scatter (half-warp split, v4.f16x2 RED, linear layout) ----------------
__global__ __launch_bounds__(256) void k_scatter(const float* __restrict__ node,
                                                 const float* __restrict__ edge,
                                                 const int* __restrict__ src,
                                                 const int* __restrict__ dst) {
    int e = blockIdx.x * 8 + (threadIdx.x >> 5);
    if (e >= N_EDGES) return;
    int lane = threadIdx.x & 31;
    int half = lane >> 4;
    int i = lane & 15;
    int s = __ldg(&src[e]);
    int d = __ldg(&dst[e]);
    const float4* e4 = reinterpret_cast<const float4*>(edge);
    const float4* n4 = reinterpret_cast<const float4*>(node);
    // streaming load of the edge row (single use — keep node table in L2)
    float4 ee = __ldcs(&e4[(size_t)e * 32 + lane]);
    float4 eA, eB;
    eA.x = __shfl_sync(0xFFFFFFFFu, ee.x, 2 * i);
    eA.y = __shfl_sync(0xFFFFFFFFu, ee.y, 2 * i);
    eA.z = __shfl_sync(0xFFFFFFFFu, ee.z, 2 * i);
    eA.w = __shfl_sync(0xFFFFFFFFu, ee.w, 2 * i);
    eB.x = __shfl_sync(0xFFFFFFFFu, ee.x, 2 * i + 1);
    eB.y = __shfl_sync(0xFFFFFFFFu, ee.y, 2 * i + 1);
    eB.z = __shfl_sync(0xFFFFFFFFu, ee.z, 2 * i + 1);
    eB.w = __shfl_sync(0xFFFFFFFFu, ee.w, 2 * i + 1);
    int nrow = half ? d : s;
    const float4* np = n4 + (size_t)nrow * 32;
    float4 nA = __ldg(&np[2 * i]);
    float4 nB = __ldg(&np[2 * i + 1]);
    __half2 m0 = __floats2half2_rn(nA.x - eA.x, nA.y - eA.y);
    __half2 m1 = __floats2half2_rn(nA.z - eA.z, nA.w - eA.w);
    __half2 m2 = __floats2half2_rn(nB.x - eB.x, nB.y - eB.y);
    __half2 m3 = __floats2half2_rn(nB.z - eB.z, nB.w - eB.w);
    __half2* base = half ? (g_acc_i + (size_t)s * 64) : (g_acc_o + (size_t)d * 64);
    red_add_h2v4(base + i * 4, m0, m1, m2, m3);
    if (lane == 0)  atomicAdd(&g_cnt[d], 1.f);
    if (lane == 16) atomicAdd(&g_cnt[N_NODES + s], 1.f);
}

// ---------------- K2: HMMA GEMM with cp.async pipeline for fp16 A tiles ----------------
// CTA: 128 rows x 128 cols, 8 warps = 4 (rows, wy) x 2 (cols, wx), warp tile 32x64.
#define NSTAGE 4
#define STG_BYTES (128 * 48)   // 128 rows x 48B (32B data + 16B pad, conflict-free ldmatrix)

__global__ __launch_bounds__(256, 2) void k_gemm(const float* __restrict__ node,
                                                 float* __restrict__ out) {
    __shared__ __align__(16) unsigned char sA[NSTAGE][STG_BYTES];
    __shared__ float s_inv[2 * 128];
    __shared__ float s_red[2 * 128];

    int tid = threadIdx.x;
    int l = tid & 31;
    int w = tid >> 5;
    int wy = w & 3;           // row group
    int wx = w >> 2;          // col group
    int row0 = blockIdx.x * 128;

    uint32_t sA_base = (uint32_t)__cvta_generic_to_shared(&sA[0][0]);

    {
        int i = tid & 127;
        int r = row0 + i;
        float v = 0.f;
        if (r < N_NODES) v = 1.f / fmaxf(g_cnt[(tid < 128 ? 0 : N_NODES) + r], 1.f);
        s_inv[tid] = v;
        if (tid < 128) { s_red[tid] = 0.f; s_red[128 + tid] = 0.f; }
    }

    // per-thread cp.async source/dest (one 16B chunk per stage)
    int crow = tid >> 1;          // 0..127
    int cchunk = tid & 1;
    int cgrow = row0 + crow;
    int cvalid = (cgrow < N_NODES) ? 16 : 0;
    uint32_t cdst_off = crow * 48 + cchunk * 16;

#define ISSUE_STAGE(t)                                                                 \
    do {                                                                               \
        if ((t) < 16) {                                                                \
            const char* _b = ((t) < 8) ? (const char*)g_acc_o : (const char*)g_acc_i;  \
            const char* _g = _b + (size_t)cgrow * 256 + ((t) & 7) * 32 + cchunk * 16;  \
            uint32_t _s = sA_base + ((t) & (NSTAGE - 1)) * STG_BYTES + cdst_off;       \
            asm volatile("cp.async.cg.shared.global [%0], [%1], 16, %2;"               \
                         :: "r"(_s), "l"(_g), "r"(cvalid));                            \
        }                                                                              \
        asm volatile("cp.async.commit_group;");                                        \
    } while (0)

    ISSUE_STAGE(0);
    ISSUE_STAGE(1);
    ISSUE_STAGE(2);
    __syncthreads();   // s_inv/s_red ready

    float acc[2][8][4];
#pragma unroll
    for (int mt = 0; mt < 2; mt++)
#pragma unroll
        for (int nt = 0; nt < 8; nt++)
#pragma unroll
            for (int q = 0; q < 4; q++) acc[mt][nt][q] = 0.f;

    const int lq = l >> 2;
    const int lk = (l & 3) * 2;

    // ---- fp16 chunks t=0..15 via smem pipeline + ldmatrix ----
    for (int t = 0; t < 16; t++) {
        asm volatile("cp.async.wait_group %0;" :: "n"(2));
        __syncthreads();

        int sel = t >> 3;
        uint32_t stg = sA_base + (t & (NSTAGE - 1)) * STG_BYTES;
        uint32_t A[2][4];
#pragma unroll
        for (int mt = 0; mt < 2; mt++) {
            int trow = wy * 32 + mt * 16 + (l & 15);
            uint32_t addr = stg + trow * 48 + (l >> 4) * 16;
            asm volatile("ldmatrix.sync.aligned.m8n8.x4.shared.b16 {%0,%1,%2,%3}, [%4];"
                         : "=r"(A[mt][0]), "=r"(A[mt][1]), "=r"(A[mt][2]), "=r"(A[mt][3])
                         : "r"(addr));
            int rbase = wy * 32 + mt * 16 + lq;
            __half2 s0 = __float2half2_rn(sel ? s_inv[128 + rbase] : s_inv[rbase]);
            __half2 s1 = __float2half2_rn(sel ? s_inv[128 + rbase + 8] : s_inv[rbase + 8]);
            A[mt][0] = hscale(A[mt][0], s0);
            A[mt][1] = hscale(A[mt][1], s1);
            A[mt][2] = hscale(A[mt][2], s0);
            A[mt][3] = hscale(A[mt][3], s1);
        }
        ISSUE_STAGE(t + 3);

        const uint4* gBt = g_Bfrag + (t * 16 + wx * 8) * 32 + l;
#pragma unroll
        for (int nt = 0; nt < 8; nt++) {
            uint4 B = __ldg(&gBt[nt * 32]);
#pragma unroll
            for (int mt = 0; mt < 2; mt++) {
                mma_fp16(acc[mt][nt], A[mt][0], A[mt][1], A[mt][2], A[mt][3], B.x, B.y);
                mma_fp16(acc[mt][nt], A[mt][0], A[mt][1], A[mt][2], A[mt][3], B.z, B.w);
            }
        }
    }

    // ---- bf16 chunks t=16..23: node embeddings, on-the-fly split (as R6) ----
#pragma unroll 2
    for (int t = 16; t < 24; t++) {
        int koff = ((t - 16) * 16 + lk) >> 1;
        uint32_t aH[2][4], aL[2][4];
#pragma unroll
        for (int mt = 0; mt < 2; mt++) {
            int ga = row0 + wy * 32 + mt * 16 + lq;
            int gb_ = ga + 8;
            const float2* b2 = reinterpret_cast<const float2*>(node);
            float2 zz = make_float2(0.f, 0.f);
            float2 p00 = (ga < N_NODES) ? __ldg(&b2[(size_t)ga * 64 + koff]) : zz;
            float2 p01 = (ga < N_NODES) ? __ldg(&b2[(size_t)ga * 64 + koff + 4]) : zz;
            float2 p10 = (gb_ < N_NODES) ? __ldg(&b2[(size_t)gb_ * 64 + koff]) : zz;
            float2 p11 = (gb_ < N_NODES) ? __ldg(&b2[(size_t)gb_ * 64 + koff + 4]) : zz;
            split2(p00, aH[mt][0], aL[mt][0]);
            split2(p10, aH[mt][1], aL[mt][1]);
            split2(p01, aH[mt][2], aL[mt][2]);
            split2(p11, aH[mt][3], aL[mt][3]);
        }
        const uint4* gBt = g_Bfrag + (t * 16 + wx * 8) * 32 + l;
#pragma unroll
        for (int nt = 0; nt < 8; nt++) {
            uint4 B = __ldg(&gBt[nt * 32]);
#pragma unroll
            for (int mt = 0; mt < 2; mt++) {
                mma_bf(acc[mt][nt], aH[mt][0], aH[mt][1], aH[mt][2], aH[mt][3], B.x, B.y);
                mma_bf(acc[mt][nt], aH[mt][0], aH[mt][1], aH[mt][2], aH[mt][3], B.z, B.w);
                mma_bf(acc[mt][nt], aL[mt][0], aL[mt][1], aL[mt][2], aL[mt][3], B.x, B.y);
            }
        }
    }

    // ---- epilogue: h = (acc + bias)/3, store, BN partial stats ----
    const float third = 1.f / 3.f;
    const float2* bias2 = reinterpret_cast<const float2*>(g_bias);
    float2* o2 = reinterpret_cast<float2*>(out);
    float ps[16], pq[16];
#pragma unroll
    for (int j = 0; j < 16; j++) { ps[j] = 0.f; pq[j] = 0.f; }

#pragma unroll
    for (int mt = 0; mt < 2; mt++) {
        int ra = row0 + wy * 32 + mt * 16 + lq;
        int rb = ra + 8;
#pragma unroll
        for (int nt = 0; nt < 8; nt++) {
            int col = wx * 64 + nt * 8 + lk;
            float2 bv = __ldg(&bias2[col >> 1]);
            if (ra < N_NODES) {
                float2 h0;
                h0.x = (acc[mt][nt][0] + bv.x) * third;
                h0.y = (acc[mt][nt][1] + bv.y) * third;
                o2[(size_t)ra * 64 + (col >> 1)] = h0;
                ps[nt * 2 + 0] += h0.x; pq[nt * 2 + 0] += h0.x * h0.x;
                ps[nt * 2 + 1] += h0.y; pq[nt * 2 + 1] += h0.y * h0.y;
            }
            if (rb < N_NODES) {
                float2 h1;
                h1.x = (acc[mt][nt][2] + bv.x) * third;
                h1.y = (acc[mt][nt][3] + bv.y) * third;
                o2[(size_t)rb * 64 + (col >> 1)] = h1;
                ps[nt * 2 + 0] += h1.x; pq[nt * 2 + 0] += h1.x * h1.x;
                ps[nt * 2 + 1] += h1.y; pq[nt * 2 + 1] += h1.y * h1.y;
            }
        }
    }
#pragma unroll
    for (int j = 0; j < 16; j++) {
        ps[j] += __shfl_xor_sync(0xFFFFFFFFu, ps[j], 4);
        ps[j] += __shfl_xor_sync(0xFFFFFFFFu, ps[j], 8);
        ps[j] += __shfl_xor_sync(0xFFFFFFFFu, ps[j], 16);
        pq[j] += __shfl_xor_sync(0xFFFFFFFFu, pq[j], 4);
        pq[j] += __shfl_xor_sync(0xFFFFFFFFu, pq[j], 8);
        pq[j] += __shfl_xor_sync(0xFFFFFFFFu, pq[j], 16);
    }
    if (l < 4) {
#pragma unroll
        for (int j = 0; j < 16; j++) {
            int col = wx * 64 + (j >> 1) * 8 + l * 2 + (j & 1);
            atomicAdd(&s_red[col], ps[j]);
            atomicAdd(&s_red[128 + col], pq[j]);
        }
    }
    __syncthreads();
    if (tid < 128) atomicAdd(&g_sum[tid], (double)s_red[tid]);
    else           atomicAdd(&g_sumsq[tid - 128], (double)s_red[tid]);
}

// ---------------- K3: BN finalize + in-place normalize (fused) ----------------
__global__ __launch_bounds__(256) void k_bn(float* __restrict__ out,
                                            const float* __restrict__ gamma,
                                            const float* __restrict__ beta) {
    __shared__ float s_aff[2 * D];   // [0:128) scale, [128:256) shift
    int tid = threadIdx.x;
    if (tid < D) {
        double mu = g_sum[tid] / (double)N_NODES;
        double var = g_sumsq[tid] / (double)N_NODES - mu * mu;
        float sc = __ldg(&gamma[tid]) * rsqrtf((float)var + BN_EPS);
        s_aff[tid] = sc;
        s_aff[D + tid] = __ldg(&beta[tid]) - (float)mu * sc;
    }
    __syncthreads();
    size_t idx = (size_t)blockIdx.x * blockDim.x + tid;
    size_t stride = (size_t)gridDim.x * blockDim.x;
    const size_t n4 = (size_t)N_NODES * D / 4;
    float4* o4 = reinterpret_cast<float4*>(out);
    const float4* sc4 = reinterpret_cast<const float4*>(s_aff);
    const float4* sh4 = reinterpret_cast<const float4*>(s_aff + D);
    for (size_t i = idx; i < n4; i += stride) {
        float4 sc = sc4[i & 31];
        float4 sh = sh4[i & 31];
        float4 v = o4[i];
        v.x = fmaf(v.x, sc.x, sh.x);
        v.y = fmaf(v.y, sc.y, sh.y);
        v.z = fmaf(v.z, sc.z, sh.z);
        v.w = fmaf(v.w, sc.w, sh.w);
        o4[i] = v;
    }
}

// ---------------- launch ----------------
extern "C" void kernel_launch(void* const* d_in, const int* in_sizes, int n_in,
                              void* d_out, int out_size) {
    const float* node  = (const float*)d_in[0];
    const float* edge  = (const float*)d_in[1];
    const float* WO    = (const float*)d_in[2];
    const float* bO    = (const float*)d_in[3];
    const float* WI    = (const float*)d_in[4];
    const float* bI    = (const float*)d_in[5];
    const float* WS    = (const float*)d_in[6];
    const float* bS    = (const float*)d_in[7];
    const float* gamma = (const float*)d_in[8];
    const float* beta  = (const float*)d_in[9];
    const int*   src   = (const int*)d_in[10];
    const int*   dst   = (const int*)d_in[11];
    float* out = (float*)d_out;

    k_init<<<1184, 256>>>(WO, WI, WS, bO, bI, bS);
    k_scatter<<<N_EDGES / 8, 256>>>(node, edge, src, dst);
    k_gemm<<<(N_NODES + 127) / 128, 256>>>(node, out);
    k_bn<<<2048, 256>>>(out, gamma, beta);
}

// round 10
// speedup vs baseline: 1.2461x; 1.0578x over previous
#include <cuda_runtime.h>
#include <cuda_bf16.h>
#include <cuda_fp16.h>
#include <cstdint>
#include <cstddef>

#define N_NODES 100000
#define N_EDGES 600000
#define D 128
#define BN_EPS 1e-5f

// ---------------- scratch (static device globals; no allocation) ----------------
__device__ __half2 g_acc_o[(size_t)N_NODES * 64];   // fp16 sums of (h_src - e) at dst
__device__ __half2 g_acc_i[(size_t)N_NODES * 64];   // fp16 sums of (h_dst - e) at src
__device__ __half2 g_node16[(size_t)N_NODES * 64];  // fp16 copy of node_embs
__device__ float  g_cnt[2 * N_NODES];               // [0:N) in-deg(dst), [N:2N) deg at src
// B fragments (ALL fp16 hi/lo split): [kstep 0..23][ntile 0..15][lane 0..31]
__device__ uint4  g_Bfrag[24 * 16 * 32];
__device__ float  g_bias[D];
__device__ double g_sum[D];
__device__ double g_sumsq[D];

// ---------------- helpers ----------------
__device__ __forceinline__ void red_add_h2v4(__half2* p, __half2 a, __half2 b,
                                             __half2 c, __half2 d) {
    asm volatile("red.global.add.noftz.v4.f16x2 [%0], {%1,%2,%3,%4};"
                 :: "l"(p),
                    "r"(*reinterpret_cast<uint32_t*>(&a)),
                    "r"(*reinterpret_cast<uint32_t*>(&b)),
                    "r"(*reinterpret_cast<uint32_t*>(&c)),
                    "r"(*reinterpret_cast<uint32_t*>(&d)) : "memory");
}

__device__ __forceinline__ void mma_fp16(float* d, uint32_t a0, uint32_t a1, uint32_t a2,
                                         uint32_t a3, uint32_t b0, uint32_t b1) {
    asm volatile(
        "mma.sync.aligned.m16n8k16.row.col.f32.f16.f16.f32 "
        "{%0,%1,%2,%3}, {%4,%5,%6,%7}, {%8,%9}, {%0,%1,%2,%3};"
        : "+f"(d[0]), "+f"(d[1]), "+f"(d[2]), "+f"(d[3])
        : "r"(a0), "r"(a1), "r"(a2), "r"(a3), "r"(b0), "r"(b1));
}

__device__ __forceinline__ void split2h(float2 v, uint32_t& h, uint32_t& l) {
    __half2 hp = __floats2half2_rn(v.x, v.y);
    float hx = __low2float(hp), hy = __high2float(hp);
    __half2 lp = __floats2half2_rn(v.x - hx, v.y - hy);
    h = *reinterpret_cast<uint32_t*>(&hp);
    l = *reinterpret_cast<uint32_t*>(&lp);
}

__device__ __forceinline__ uint32_t hscale(uint32_t u, __half2 s) {
    __half2 v = *reinterpret_cast<__half2*>(&u);
    v = __hmul2(v, s);
    return *reinterpret_cast<uint32_t*>(&v);
}

// ---------------- K0: zero scratch + fp16 node table + pack W + bias ----------------
__global__ void k_init(const float* __restrict__ node,
                       const float* __restrict__ WO, const float* __restrict__ WI,
                       const float* __restrict__ WS, const float* __restrict__ bO,
                       const float* __restrict__ bI, const float* __restrict__ bS) {
    size_t idx = (size_t)blockIdx.x * blockDim.x + threadIdx.x;
    size_t stride = (size_t)gridDim.x * blockDim.x;
    const size_t n4 = (size_t)N_NODES * 16;
    uint4 z = make_uint4(0, 0, 0, 0);
    uint4* ao = reinterpret_cast<uint4*>(g_acc_o);
    uint4* ai = reinterpret_cast<uint4*>(g_acc_i);
    for (size_t i = idx; i < n4; i += stride) { ao[i] = z; ai[i] = z; }
    // node fp32 -> fp16 table
    const float2* nsrc = reinterpret_cast<const float2*>(node);
    const size_t nh2 = (size_t)N_NODES * 64;
    for (size_t i = idx; i < nh2; i += stride) {
        float2 v = __ldg(&nsrc[i]);
        g_node16[i] = __floats2half2_rn(v.x, v.y);
    }
    float4 zf = make_float4(0.f, 0.f, 0.f, 0.f);
    float4* cp = reinterpret_cast<float4*>(g_cnt);
    for (size_t i = idx; i < (2 * N_NODES) / 4; i += stride) cp[i] = zf;
    if (idx < D) { g_sum[idx] = 0.0; g_sumsq[idx] = 0.0; g_bias[idx] = bO[idx] + bI[idx] + bS[idx]; }
    if (idx < 24 * 16 * 32) {
        int t  = (int)idx >> 9;
        int nt = ((int)idx >> 5) & 15;
        int l  = (int)idx & 31;
        int n  = nt * 8 + (l >> 2);
        int kg = t * 16 + (l & 3) * 2;
        const float* Wsrc = (kg < 128) ? WO : ((kg < 256) ? WI : WS);
        int kk = kg & 127;
        float w00 = __ldg(&Wsrc[n * 128 + kk]);
        float w01 = __ldg(&Wsrc[n * 128 + kk + 1]);
        float w10 = __ldg(&Wsrc[n * 128 + kk + 8]);
        float w11 = __ldg(&Wsrc[n * 128 + kk + 9]);
        uint32_t b0h, b0l, b1h, b1l;
        split2h(make_float2(w00, w01), b0h, b0l);
        split2h(make_float2(w10, w11), b1h, b1l);
        g_Bfrag[idx] = make_uint4(b0h, b1h, b0l, b1l);
    }
}

// ---------------- K1: edge scatter (fp16 node reads, v4.f16x2 RED) ----------------
__global__ __launch_bounds__(256) void k_scatter(const float* __restrict__ edge,
                                                 const int* __restrict__ src,
                                                 const int* __restrict__ dst) {
    int e = blockIdx.x * 8 + (threadIdx.x >> 5);
    if (e >= N_EDGES) return;
    int lane = threadIdx.x & 31;
    int half = lane >> 4;
    int i = lane & 15;
    int s = __ldg(&src[e]);
    int d = __ldg(&dst[e]);
    const float4* e4 = reinterpret_cast<const float4*>(edge);
    // streaming load of the edge row (single use — keep node/acc tables in L2)
    float4 ee = __ldcs(&e4[(size_t)e * 32 + lane]);
    float4 eA, eB;
    eA.x = __shfl_sync(0xFFFFFFFFu, ee.x, 2 * i);
    eA.y = __shfl_sync(0xFFFFFFFFu, ee.y, 2 * i);
    eA.z = __shfl_sync(0xFFFFFFFFu, ee.z, 2 * i);
    eA.w = __shfl_sync(0xFFFFFFFFu, ee.w, 2 * i);
    eB.x = __shfl_sync(0xFFFFFFFFu, ee.x, 2 * i + 1);
    eB.y = __shfl_sync(0xFFFFFFFFu, ee.y, 2 * i + 1);
    eB.z = __shfl_sync(0xFFFFFFFFu, ee.z, 2 * i + 1);
    eB.w = __shfl_sync(0xFFFFFFFFu, ee.w, 2 * i + 1);
    int nrow = half ? d : s;
    const uint4* n16 = reinterpret_cast<const uint4*>(g_node16);
    uint4 nv = __ldg(&n16[(size_t)nrow * 16 + i]);   // elements 8i..8i+7 as 4x half2
    float2 f0 = __half22float2(*reinterpret_cast<__half2*>(&nv.x));
    float2 f1 = __half22float2(*reinterpret_cast<__half2*>(&nv.y));
    float2 f2 = __half22float2(*reinterpret_cast<__half2*>(&nv.z));
    float2 f3 = __half22float2(*reinterpret_cast<__half2*>(&nv.w));
    __half2 m0 = __floats2half2_rn(f0.x - eA.x, f0.y - eA.y);
    __half2 m1 = __floats2half2_rn(f1.x - eA.z, f1.y - eA.w);
    __half2 m2 = __floats2half2_rn(f2.x - eB.x, f2.y - eB.y);
    __half2 m3 = __floats2half2_rn(f3.x - eB.z, f3.y - eB.w);
    __half2* base = half ? (g_acc_i + (size_t)s * 64) : (g_acc_o + (size_t)d * 64);
    red_add_h2v4(base + i * 4, m0, m1, m2, m3);
    if (lane == 0)  atomicAdd(&g_cnt[d], 1.f);
    if (lane == 16) atomicAdd(&g_cnt[N_NODES + s], 1.f);
}

// ---------------- K2: uniform fp16 HMMA GEMM, cp.async pipeline for all A tiles ----------------
// CTA: 128 rows x 128 cols, 8 warps = 4 (rows, wy) x 2 (cols, wx), warp tile 32x64.
#define NSTAGE 4
#define STG_BYTES (128 * 48)   // 128 rows x (32B data + 16B pad)

__global__ __launch_bounds__(256, 2) void k_gemm(float* __restrict__ out) {
    __shared__ __align__(16) unsigned char sA[NSTAGE][STG_BYTES];
    __shared__ float s_inv[2 * 128];
    __shared__ float s_red[2 * 128];

    int tid = threadIdx.x;
    int l = tid & 31;
    int w = tid >> 5;
    int wy = w & 3;           // row group
    int wx = w >> 2;          // col group
    int row0 = blockIdx.x * 128;

    uint32_t sA_base = (uint32_t)__cvta_generic_to_shared(&sA[0][0]);

    {
        int i = tid & 127;
        int r = row0 + i;
        float v = 0.f;
        if (r < N_NODES) v = 1.f / fmaxf(g_cnt[(tid < 128 ? 0 : N_NODES) + r], 1.f);
        s_inv[tid] = v;
        if (tid < 128) { s_red[tid] = 0.f; s_red[128 + tid] = 0.f; }
    }

    // per-thread cp.async source/dest (one 16B chunk per stage)
    int crow = tid >> 1;
    int cchunk = tid & 1;
    int cgrow = row0 + crow;
    int cvalid = (cgrow < N_NODES) ? 16 : 0;
    uint32_t cdst_off = crow * 48 + cchunk * 16;

#define ISSUE_STAGE(t)                                                                   \
    do {                                                                                 \
        if ((t) < 24) {                                                                  \
            const char* _b = ((t) < 8) ? (const char*)g_acc_o                            \
                           : ((t) < 16) ? (const char*)g_acc_i : (const char*)g_node16;  \
            const char* _g = _b + (size_t)cgrow * 256 + ((t) & 7) * 32 + cchunk * 16;    \
            uint32_t _s = sA_base + ((t) & (NSTAGE - 1)) * STG_BYTES + cdst_off;         \
            asm volatile("cp.async.cg.shared.global [%0], [%1], 16, %2;"                 \
                         :: "r"(_s), "l"(_g), "r"(cvalid));                              \
        }                                                                                \
        asm volatile("cp.async.commit_group;");                                          \
    } while (0)

    ISSUE_STAGE(0);
    ISSUE_STAGE(1);
    ISSUE_STAGE(2);
    __syncthreads();   // s_inv/s_red ready

    float acc[2][8][4];
#pragma unroll
    for (int mt = 0; mt < 2; mt++)
#pragma unroll
        for (int nt = 0; nt < 8; nt++)
#pragma unroll
            for (int q = 0; q < 4; q++) acc[mt][nt][q] = 0.f;

    const int lq = l >> 2;
    const int lk = (l & 3) * 2;

    for (int t = 0; t < 24; t++) {
        asm volatile("cp.async.wait_group %0;" :: "n"(2));
        __syncthreads();

        uint32_t stg = sA_base + (t & (NSTAGE - 1)) * STG_BYTES;
        uint32_t A[2][4];
#pragma unroll
        for (int mt = 0; mt < 2; mt++) {
            int trow = wy * 32 + mt * 16 + (l & 15);
            uint32_t addr = stg + trow * 48 + (l >> 4) * 16;
            asm volatile("ldmatrix.sync.aligned.m8n8.x4.shared.b16 {%0,%1,%2,%3}, [%4];"
                         : "=r"(A[mt][0]), "=r"(A[mt][1]), "=r"(A[mt][2]), "=r"(A[mt][3])
                         : "r"(addr));
            if (t < 16) {
                int sel = t >> 3;
                int rbase = wy * 32 + mt * 16 + lq;
                __half2 s0 = __float2half2_rn(sel ? s_inv[128 + rbase] : s_inv[rbase]);
                __half2 s1 = __float2half2_rn(sel ? s_inv[128 + rbase + 8] : s_inv[rbase + 8]);
                A[mt][0] = hscale(A[mt][0], s0);
                A[mt][1] = hscale(A[mt][1], s1);
                A[mt][2] = hscale(A[mt][2], s0);
                A[mt][3] = hscale(A[mt][3], s1);
            }
        }
        ISSUE_STAGE(t + 3);

        const uint4* gBt = g_Bfrag + (t * 16 + wx * 8) * 32 + l;
#pragma unroll
        for (int nt = 0; nt < 8; nt++) {
            uint4 B = __ldg(&gBt[nt * 32]);
#pragma unroll
            for (int mt = 0; mt < 2; mt++) {
                mma_fp16(acc[mt][nt], A[mt][0], A[mt][1], A[mt][2], A[mt][3], B.x, B.y);
                mma_fp16(acc[mt][nt], A[mt][0], A[mt][1], A[mt][2], A[mt][3], B.z, B.w);
            }
        }
    }

    // ---- epilogue: h = (acc + bias)/3, store, BN partial stats ----
    const float third = 1.f / 3.f;
    const float2* bias2 = reinterpret_cast<const float2*>(g_bias);
    float2* o2 = reinterpret_cast<float2*>(out);
    float ps[16], pq[16];
#pragma unroll
    for (int j = 0; j < 16; j++) { ps[j] = 0.f; pq[j] = 0.f; }

#pragma unroll
    for (int mt = 0; mt < 2; mt++) {
        int ra = row0 + wy * 32 + mt * 16 + lq;
        int rb = ra + 8;
#pragma unroll
        for (int nt = 0; nt < 8; nt++) {
            int col = wx * 64 + nt * 8 + lk;
            float2 bv = __ldg(&bias2[col >> 1]);
            if (ra < N_NODES) {
                float2 h0;
                h0.x = (acc[mt][nt][0] + bv.x) * third;
                h0.y = (acc[mt][nt][1] + bv.y) * third;
                o2[(size_t)ra * 64 + (col >> 1)] = h0;
                ps[nt * 2 + 0] += h0.x; pq[nt * 2 + 0] += h0.x * h0.x;
                ps[nt * 2 + 1] += h0.y; pq[nt * 2 + 1] += h0.y * h0.y;
            }
            if (rb < N_NODES) {
                float2 h1;
                h1.x = (acc[mt][nt][2] + bv.x) * third;
                h1.y = (acc[mt][nt][3] + bv.y) * third;
                o2[(size_t)rb * 64 + (col >> 1)] = h1;
                ps[nt * 2 + 0] += h1.x; pq[nt * 2 + 0] += h1.x * h1.x;
                ps[nt * 2 + 1] += h1.y; pq[nt * 2 + 1] += h1.y * h1.y;
            }
        }
    }
#pragma unroll
    for (int j = 0; j < 16; j++) {
        ps[j] += __shfl_xor_sync(0xFFFFFFFFu, ps[j], 4);
        ps[j] += __shfl_xor_sync(0xFFFFFFFFu, ps[j], 8);
        ps[j] += __shfl_xor_sync(0xFFFFFFFFu, ps[j], 16);
        pq[j] += __shfl_xor_sync(0xFFFFFFFFu, pq[j], 4);
        pq[j] += __shfl_xor_sync(0xFFFFFFFFu, pq[j], 8);
        pq[j] += __shfl_xor_sync(0xFFFFFFFFu, pq[j], 16);
    }
    if (l < 4) {
#pragma unroll
        for (int j = 0; j < 16; j++) {
            int col = wx * 64 + (j >> 1) * 8 + l * 2 + (j & 1);
            atomicAdd(&s_red[col], ps[j]);
            atomicAdd(&s_red[128 + col], pq[j]);
        }
    }
    __syncthreads();
    if (tid < 128) atomicAdd(&g_sum[tid], (double)s_red[tid]);
    else           atomicAdd(&g_sumsq[tid - 128], (double)s_red[tid]);
}

// ---------------- K3: BN finalize + in-place normalize (fused) ----------------
__global__ __launch_bounds__(256) void k_bn(float* __restrict__ out,
                                            const float* __restrict__ gamma,
                                            const float* __restrict__ beta) {
    __shared__ float s_aff[2 * D];
    int tid = threadIdx.x;
    if (tid < D) {
        double mu = g_sum[tid] / (double)N_NODES;
        double var = g_sumsq[tid] / (double)N_NODES - mu * mu;
        float sc = __ldg(&gamma[tid]) * rsqrtf((float)var + BN_EPS);
        s_aff[tid] = sc;
        s_aff[D + tid] = __ldg(&beta[tid]) - (float)mu * sc;
    }
    __syncthreads();
    size_t idx = (size_t)blockIdx.x * blockDim.x + tid;
    size_t stride = (size_t)gridDim.x * blockDim.x;
    const size_t n4 = (size_t)N_NODES * D / 4;
    float4* o4 = reinterpret_cast<float4*>(out);
    const float4* sc4 = reinterpret_cast<const float4*>(s_aff);
    const float4* sh4 = reinterpret_cast<const float4*>(s_aff + D);
    for (size_t i = idx; i < n4; i += stride) {
        float4 sc = sc4[i & 31];
        float4 sh = sh4[i & 31];
        float4 v = o4[i];
        v.x = fmaf(v.x, sc.x, sh.x);
        v.y = fmaf(v.y, sc.y, sh.y);
        v.z = fmaf(v.z, sc.z, sh.z);
        v.w = fmaf(v.w, sc.w, sh.w);
        o4[i] = v;
    }
}

// ---------------- launch ----------------
extern "C" void kernel_launch(void* const* d_in, const int* in_sizes, int n_in,
                              void* d_out, int out_size) {
    const float* node  = (const float*)d_in[0];
    const float* edge  = (const float*)d_in[1];
    const float* WO    = (const float*)d_in[2];
    const float* bO    = (const float*)d_in[3];
    const float* WI    = (const float*)d_in[4];
    const float* bI    = (const float*)d_in[5];
    const float* WS    = (const float*)d_in[6];
    const float* bS    = (const float*)d_in[7];
    const float* gamma = (const float*)d_in[8];
    const float* beta  = (const float*)d_in[9];
    const int*   src   = (const int*)d_in[10];
    const int*   dst   = (const int*)d_in[11];
    float* out = (float*)d_out;

    k_init<<<1184, 256>>>(node, WO, WI, WS, bO, bI, bS);
    k_scatter<<<N_EDGES / 8, 256>>>(edge, src, dst);
    k_gemm<<<(N_NODES + 127) / 128, 256>>>(out);
    k_bn<<<2048, 256>>>(out, gamma, beta);
}

// round 11
// speedup vs baseline: 1.3154x; 1.0557x over previous
#include <cuda_runtime.h>
#include <cuda_bf16.h>
#include <cuda_fp16.h>
#include <cstdint>
#include <cstddef>

#define N_NODES 100000
#define N_EDGES 600000
#define D 128
#define BN_EPS 1e-5f

// ---------------- scratch (static device globals; no allocation) ----------------
__device__ __half2 g_acc_o[(size_t)N_NODES * 64];   // fp16 sums of (h_src - e) at dst
__device__ __half2 g_acc_i[(size_t)N_NODES * 64];   // fp16 sums of (h_dst - e) at src
__device__ __half2 g_node16[(size_t)N_NODES * 64];  // fp16 copy of node_embs
__device__ float  g_cnt[2 * N_NODES];               // [0:N) in-deg(dst), [N:2N) deg at src
// B fragments (fp16, hi only): [kstep 0..23][ntile 0..15][lane 0..31] = (b0,b1)
__device__ uint2  g_Bfrag[24 * 16 * 32];
__device__ float  g_bias[D];
__device__ double g_sum[D];
__device__ double g_sumsq[D];

// ---------------- helpers ----------------
__device__ __forceinline__ void red_add_h2v4(__half2* p, __half2 a, __half2 b,
                                             __half2 c, __half2 d) {
    asm volatile("red.global.add.noftz.v4.f16x2 [%0], {%1,%2,%3,%4};"
                 :: "l"(p),
                    "r"(*reinterpret_cast<uint32_t*>(&a)),
                    "r"(*reinterpret_cast<uint32_t*>(&b)),
                    "r"(*reinterpret_cast<uint32_t*>(&c)),
                    "r"(*reinterpret_cast<uint32_t*>(&d)) : "memory");
}

__device__ __forceinline__ void mma_fp16(float* d, uint32_t a0, uint32_t a1, uint32_t a2,
                                         uint32_t a3, uint32_t b0, uint32_t b1) {
    asm volatile(
        "mma.sync.aligned.m16n8k16.row.col.f32.f16.f16.f32 "
        "{%0,%1,%2,%3}, {%4,%5,%6,%7}, {%8,%9}, {%0,%1,%2,%3};"
        : "+f"(d[0]), "+f"(d[1]), "+f"(d[2]), "+f"(d[3])
        : "r"(a0), "r"(a1), "r"(a2), "r"(a3), "r"(b0), "r"(b1));
}

__device__ __forceinline__ uint32_t hscale(uint32_t u, __half2 s) {
    __half2 v = *reinterpret_cast<__half2*>(&u);
    v = __hmul2(v, s);
    return *reinterpret_cast<uint32_t*>(&v);
}

// ---------------- K0: zero scratch + fp16 node table + pack W + bias ----------------
__global__ void k_init(const float* __restrict__ node,
                       const float* __restrict__ WO, const float* __restrict__ WI,
                       const float* __restrict__ WS, const float* __restrict__ bO,
                       const float* __restrict__ bI, const float* __restrict__ bS) {
    size_t idx = (size_t)blockIdx.x * blockDim.x + threadIdx.x;
    size_t stride = (size_t)gridDim.x * blockDim.x;
    const size_t n4 = (size_t)N_NODES * 16;
    uint4 z = make_uint4(0, 0, 0, 0);
    uint4* ao = reinterpret_cast<uint4*>(g_acc_o);
    uint4* ai = reinterpret_cast<uint4*>(g_acc_i);
    for (size_t i = idx; i < n4; i += stride) { ao[i] = z; ai[i] = z; }
    const float2* nsrc = reinterpret_cast<const float2*>(node);
    const size_t nh2 = (size_t)N_NODES * 64;
    for (size_t i = idx; i < nh2; i += stride) {
        float2 v = __ldg(&nsrc[i]);
        g_node16[i] = __floats2half2_rn(v.x, v.y);
    }
    float4 zf = make_float4(0.f, 0.f, 0.f, 0.f);
    float4* cp = reinterpret_cast<float4*>(g_cnt);
    for (size_t i = idx; i < (2 * N_NODES) / 4; i += stride) cp[i] = zf;
    if (idx < D) { g_sum[idx] = 0.0; g_sumsq[idx] = 0.0; g_bias[idx] = bO[idx] + bI[idx] + bS[idx]; }
    if (idx < 24 * 16 * 32) {
        int t  = (int)idx >> 9;
        int nt = ((int)idx >> 5) & 15;
        int l  = (int)idx & 31;
        int n  = nt * 8 + (l >> 2);
        int kg = t * 16 + (l & 3) * 2;
        const float* Wsrc = (kg < 128) ? WO : ((kg < 256) ? WI : WS);
        int kk = kg & 127;
        float w00 = __ldg(&Wsrc[n * 128 + kk]);
        float w01 = __ldg(&Wsrc[n * 128 + kk + 1]);
        float w10 = __ldg(&Wsrc[n * 128 + kk + 8]);
        float w11 = __ldg(&Wsrc[n * 128 + kk + 9]);
        __half2 b0 = __floats2half2_rn(w00, w01);
        __half2 b1 = __floats2half2_rn(w10, w11);
        g_Bfrag[idx] = make_uint2(*reinterpret_cast<uint32_t*>(&b0),
                                  *reinterpret_cast<uint32_t*>(&b1));
    }
}

// ---------------- K1: edge scatter (fp16 node reads, direct edge loads) ----------------
__global__ __launch_bounds__(256) void k_scatter(const float* __restrict__ edge,
                                                 const int* __restrict__ src,
                                                 const int* __restrict__ dst) {
    int e = blockIdx.x * 8 + (threadIdx.x >> 5);
    if (e >= N_EDGES) return;
    int lane = threadIdx.x & 31;
    int half = lane >> 4;
    int i = lane & 15;
    int s = __ldg(&src[e]);
    int d = __ldg(&dst[e]);
    const float4* ep = reinterpret_cast<const float4*>(edge) + (size_t)e * 32;
    // both half-warps read the same sectors; L1 serves the duplicates
    float4 eA = __ldcs(&ep[2 * i]);
    float4 eB = __ldcs(&ep[2 * i + 1]);
    int nrow = half ? d : s;
    const uint4* n16 = reinterpret_cast<const uint4*>(g_node16);
    uint4 nv = __ldg(&n16[(size_t)nrow * 16 + i]);   // elements 8i..8i+7 as 4x half2
    float2 f0 = __half22float2(*reinterpret_cast<__half2*>(&nv.x));
    float2 f1 = __half22float2(*reinterpret_cast<__half2*>(&nv.y));
    float2 f2 = __half22float2(*reinterpret_cast<__half2*>(&nv.z));
    float2 f3 = __half22float2(*reinterpret_cast<__half2*>(&nv.w));
    __half2 m0 = __floats2half2_rn(f0.x - eA.x, f0.y - eA.y);
    __half2 m1 = __floats2half2_rn(f1.x - eA.z, f1.y - eA.w);
    __half2 m2 = __floats2half2_rn(f2.x - eB.x, f2.y - eB.y);
    __half2 m3 = __floats2half2_rn(f3.x - eB.z, f3.y - eB.w);
    __half2* base = half ? (g_acc_i + (size_t)s * 64) : (g_acc_o + (size_t)d * 64);
    red_add_h2v4(base + i * 4, m0, m1, m2, m3);
    if (lane == 0)  atomicAdd(&g_cnt[d], 1.f);
    if (lane == 16) atomicAdd(&g_cnt[N_NODES + s], 1.f);
}

// ---------------- K2: fp16 HMMA GEMM, 2-kstep cp.async stages ----------------
// CTA: 128 rows x 128 cols, 8 warps = 4 (rows, wy) x 2 (cols, wx), warp tile 32x64.
#define NSTAGE 4
#define ROW_B 80                       // 64B data + 16B pad (conflict-free ldmatrix)
#define STG_BYTES (128 * ROW_B)

__global__ __launch_bounds__(256, 2) void k_gemm(float* __restrict__ out) {
    __shared__ __align__(16) unsigned char sA[NSTAGE][STG_BYTES];
    __shared__ float s_inv[2 * 128];
    __shared__ float s_red[2 * 128];

    int tid = threadIdx.x;
    int l = tid & 31;
    int w = tid >> 5;
    int wy = w & 3;           // row group
    int wx = w >> 2;          // col group
    int row0 = blockIdx.x * 128;

    uint32_t sA_base = (uint32_t)__cvta_generic_to_shared(&sA[0][0]);

    {
        int i = tid & 127;
        int r = row0 + i;
        float v = 0.f;
        if (r < N_NODES) v = 1.f / fmaxf(g_cnt[(tid < 128 ? 0 : N_NODES) + r], 1.f);
        s_inv[tid] = v;
        if (tid < 128) { s_red[tid] = 0.f; s_red[128 + tid] = 0.f; }
    }

    // per-thread cp.async: row tid>>1, 32B half (tid&1) of the 64B row-chunk
    int crow = tid >> 1;
    int chalf = tid & 1;
    int cgrow = row0 + crow;
    int cvalid = (cgrow < N_NODES) ? 16 : 0;
    uint32_t cdst = crow * ROW_B + chalf * 32;

#define ISSUE_STAGE(st)                                                                  \
    do {                                                                                 \
        if ((st) < 12) {                                                                 \
            const char* _b = ((st) < 4) ? (const char*)g_acc_o                           \
                           : ((st) < 8) ? (const char*)g_acc_i : (const char*)g_node16;  \
            const char* _g = _b + (size_t)cgrow * 256 + ((st) & 3) * 64 + chalf * 32;    \
            uint32_t _s = sA_base + ((st) & (NSTAGE - 1)) * STG_BYTES + cdst;            \
            asm volatile("cp.async.cg.shared.global [%0], [%1], 16, %2;"                 \
                         :: "r"(_s), "l"(_g), "r"(cvalid));                              \
            asm volatile("cp.async.cg.shared.global [%0], [%1], 16, %2;"                 \
                         :: "r"(_s + 16), "l"(_g + 16), "r"(cvalid));                    \
        }                                                                                \
        asm volatile("cp.async.commit_group;");                                          \
    } while (0)

    ISSUE_STAGE(0);
    ISSUE_STAGE(1);
    ISSUE_STAGE(2);
    __syncthreads();   // s_inv/s_red ready

    float acc[2][8][4];
#pragma unroll
    for (int mt = 0; mt < 2; mt++)
#pragma unroll
        for (int nt = 0; nt < 8; nt++)
#pragma unroll
            for (int q = 0; q < 4; q++) acc[mt][nt][q] = 0.f;

    const int lq = l >> 2;
    const int lk = (l & 3) * 2;

    // per-row fp16 inverse-degree scales (o and i)
    __half2 sco[2][2], sci[2][2];
#pragma unroll
    for (int mt = 0; mt < 2; mt++) {
        int rbase = wy * 32 + mt * 16 + lq;
        sco[mt][0] = __float2half2_rn(s_inv[rbase]);
        sco[mt][1] = __float2half2_rn(s_inv[rbase + 8]);
        sci[mt][0] = __float2half2_rn(s_inv[128 + rbase]);
        sci[mt][1] = __float2half2_rn(s_inv[128 + rbase + 8]);
    }

    for (int st = 0; st < 12; st++) {
        asm volatile("cp.async.wait_group %0;" :: "n"(2));
        __syncthreads();

        uint32_t stg = sA_base + (st & (NSTAGE - 1)) * STG_BYTES;
        uint32_t A[2][2][4];    // [sub][mt][frag]
#pragma unroll
        for (int sub = 0; sub < 2; sub++) {
#pragma unroll
            for (int mt = 0; mt < 2; mt++) {
                int trow = wy * 32 + mt * 16 + (l & 15);
                uint32_t addr = stg + trow * ROW_B + sub * 32 + (l >> 4) * 16;
                asm volatile("ldmatrix.sync.aligned.m8n8.x4.shared.b16 {%0,%1,%2,%3}, [%4];"
                             : "=r"(A[sub][mt][0]), "=r"(A[sub][mt][1]),
                               "=r"(A[sub][mt][2]), "=r"(A[sub][mt][3])
                             : "r"(addr));
                if (st < 8) {
                    const __half2* sc = (st < 4) ? sco[mt] : sci[mt];
                    A[sub][mt][0] = hscale(A[sub][mt][0], sc[0]);
                    A[sub][mt][1] = hscale(A[sub][mt][1], sc[1]);
                    A[sub][mt][2] = hscale(A[sub][mt][2], sc[0]);
                    A[sub][mt][3] = hscale(A[sub][mt][3], sc[1]);
                }
            }
        }
        ISSUE_STAGE(st + 3);

#pragma unroll
        for (int sub = 0; sub < 2; sub++) {
            int t = st * 2 + sub;
            const uint2* gBt = g_Bfrag + (t * 16 + wx * 8) * 32 + l;
#pragma unroll
            for (int nt = 0; nt < 8; nt++) {
                uint2 B = __ldg(&gBt[nt * 32]);
#pragma unroll
                for (int mt = 0; mt < 2; mt++) {
                    mma_fp16(acc[mt][nt], A[sub][mt][0], A[sub][mt][1],
                             A[sub][mt][2], A[sub][mt][3], B.x, B.y);
                }
            }
        }
    }

    // ---- epilogue: h = (acc + bias)/3, store, BN partial stats ----
    const float third = 1.f / 3.f;
    const float2* bias2 = reinterpret_cast<const float2*>(g_bias);
    float2* o2 = reinterpret_cast<float2*>(out);
    float ps[16], pq[16];
#pragma unroll
    for (int j = 0; j < 16; j++) { ps[j] = 0.f; pq[j] = 0.f; }

#pragma unroll
    for (int mt = 0; mt < 2; mt++) {
        int ra = row0 + wy * 32 + mt * 16 + lq;
        int rb = ra + 8;
#pragma unroll
        for (int nt = 0; nt < 8; nt++) {
            int col = wx * 64 + nt * 8 + lk;
            float2 bv = __ldg(&bias2[col >> 1]);
            if (ra < N_NODES) {
                float2 h0;
                h0.x = (acc[mt][nt][0] + bv.x) * third;
                h0.y = (acc[mt][nt][1] + bv.y) * third;
                o2[(size_t)ra * 64 + (col >> 1)] = h0;
                ps[nt * 2 + 0] += h0.x; pq[nt * 2 + 0] += h0.x * h0.x;
                ps[nt * 2 + 1] += h0.y; pq[nt * 2 + 1] += h0.y * h0.y;
            }
            if (rb < N_NODES) {
                float2 h1;
                h1.x = (acc[mt][nt][2] + bv.x) * third;
                h1.y = (acc[mt][nt][3] + bv.y) * third;
                o2[(size_t)rb * 64 + (col >> 1)] = h1;
                ps[nt * 2 + 0] += h1.x; pq[nt * 2 + 0] += h1.x * h1.x;
                ps[nt * 2 + 1] += h1.y; pq[nt * 2 + 1] += h1.y * h1.y;
            }
        }
    }
#pragma unroll
    for (int j = 0; j < 16; j++) {
        ps[j] += __shfl_xor_sync(0xFFFFFFFFu, ps[j], 4);
        ps[j] += __shfl_xor_sync(0xFFFFFFFFu, ps[j], 8);
        ps[j] += __shfl_xor_sync(0xFFFFFFFFu, ps[j], 16);
        pq[j] += __shfl_xor_sync(0xFFFFFFFFu, pq[j], 4);
        pq[j] += __shfl_xor_sync(0xFFFFFFFFu, pq[j], 8);
        pq[j] += __shfl_xor_sync(0xFFFFFFFFu, pq[j], 16);
    }
    if (l < 4) {
#pragma unroll
        for (int j = 0; j < 16; j++) {
            int col = wx * 64 + (j >> 1) * 8 + l * 2 + (j & 1);
            atomicAdd(&s_red[col], ps[j]);
            atomicAdd(&s_red[128 + col], pq[j]);
        }
    }
    __syncthreads();
    if (tid < 128) atomicAdd(&g_sum[tid], (double)s_red[tid]);
    else           atomicAdd(&g_sumsq[tid - 128], (double)s_red[tid]);
}

// ---------------- K3: BN finalize + in-place normalize (fused) ----------------
__global__ __launch_bounds__(256) void k_bn(float* __restrict__ out,
                                            const float* __restrict__ gamma,
                                            const float* __restrict__ beta) {
    __shared__ float s_aff[2 * D];
    int tid = threadIdx.x;
    if (tid < D) {
        double mu = g_sum[tid] / (double)N_NODES;
        double var = g_sumsq[tid] / (double)N_NODES - mu * mu;
        float sc = __ldg(&gamma[tid]) * rsqrtf((float)var + BN_EPS);
        s_aff[tid] = sc;
        s_aff[D + tid] = __ldg(&beta[tid]) - (float)mu * sc;
    }
    __syncthreads();
    size_t idx = (size_t)blockIdx.x * blockDim.x + tid;
    size_t stride = (size_t)gridDim.x * blockDim.x;
    const size_t n4 = (size_t)N_NODES * D / 4;
    float4* o4 = reinterpret_cast<float4*>(out);
    const float4* sc4 = reinterpret_cast<const float4*>(s_aff);
    const float4* sh4 = reinterpret_cast<const float4*>(s_aff + D);
    for (size_t i = idx; i < n4; i += stride) {
        float4 sc = sc4[i & 31];
        float4 sh = sh4[i & 31];
        float4 v = o4[i];
        v.x = fmaf(v.x, sc.x, sh.x);
        v.y = fmaf(v.y, sc.y, sh.y);
        v.z = fmaf(v.z, sc.z, sh.z);
        v.w = fmaf(v.w, sc.w, sh.w);
        o4[i] = v;
    }
}

// ---------------- launch ----------------
extern "C" void kernel_launch(void* const* d_in, const int* in_sizes, int n_in,
                              void* d_out, int out_size) {
    const float* node  = (const float*)d_in[0];
    const float* edge  = (const float*)d_in[1];
    const float* WO    = (const float*)d_in[2];
    const float* bO    = (const float*)d_in[3];
    const float* WI    = (const float*)d_in[4];
    const float* bI    = (const float*)d_in[5];
    const float* WS    = (const float*)d_in[6];
    const float* bS    = (const float*)d_in[7];
    const float* gamma = (const float*)d_in[8];
    const float* beta  = (const float*)d_in[9];
    const int*   src   = (const int*)d_in[10];
    const int*   dst   = (const int*)d_in[11];
    float* out = (float*)d_out;

    k_init<<<1184, 256>>>(node, WO, WI, WS, bO, bI, bS);
    k_scatter<<<N_EDGES / 8, 256>>>(edge, src, dst);
    k_gemm<<<(N_NODES + 127) / 128, 256>>>(out);
    k_bn<<<2048, 256>>>(out, gamma, beta);
}